// round 3
// baseline (speedup 1.0000x reference)
#include <cuda_runtime.h>
#include <cstdint>

#define BB 128
#define TT 1024
#define HH 256
#define RW 192           // W_hh columns in registers per thread (96 f32x2 pairs)
#define SW 64            // W_hh columns in shared memory (16 groups of 4)

typedef unsigned long long ull;

// scratch: per-row squared norms of p
__device__ float g_sq[BB * TT];

// ---------------- packed fp32x2 helpers (Blackwell FFMA2) ----------------
__device__ __forceinline__ void ffma2(ull& acc, ull a, ull b) {
    asm("fma.rn.f32x2 %0, %1, %2, %3;" : "=l"(acc) : "l"(a), "l"(b), "l"(acc));
}
__device__ __forceinline__ float2 unpack2(ull v) {
    unsigned lo, hi;
    asm("mov.b64 {%0, %1}, %2;" : "=r"(lo), "=r"(hi) : "l"(v));
    return make_float2(__uint_as_float(lo), __uint_as_float(hi));
}
__device__ __forceinline__ ull pack2(float lo, float hi) {
    ull r;
    asm("mov.b64 %0, {%1, %2};" : "=l"(r) : "r"(__float_as_uint(lo)), "r"(__float_as_uint(hi)));
    return r;
}

// ---------------------------------------------------------------------------
// RNN kernel: one block per batch, thread j owns output neuron j.
// W_hh row j: first RW entries live in registers as f32x2 pairs (loaded
// directly as 64-bit — no packing), last SW entries in SMEM as ulonglong2.
// ---------------------------------------------------------------------------
__global__ void __launch_bounds__(256, 1) rnn_kernel(
    const float* __restrict__ x,   const float* __restrict__ W1,
    const float* __restrict__ b1,  const float* __restrict__ W2,
    const float* __restrict__ b2,  const float* __restrict__ Wih,
    const float* __restrict__ Whh, float* __restrict__ p_out)
{
    extern __shared__ float sm[];
    float* hbuf = sm;                                  // 2 * 256 (ping-pong h)
    float* hid  = sm + 512;                            // 64
    ulonglong2* Ws = reinterpret_cast<ulonglong2*>(sm + 576);  // (SW/4) * 256 entries

    const int j = threadIdx.x;
    const int b = blockIdx.x;

    // stage SMEM weight chunk: Ws[g*256+j] = Whh[j][RW+4g .. +3] (bit-identical copy)
    for (int g = 0; g < SW / 4; ++g) {
        float4 w = *reinterpret_cast<const float4*>(Whh + (size_t)j * HH + RW + 4 * g);
        Ws[g * HH + j] = *reinterpret_cast<const ulonglong2*>(&w);
    }

    // register weight chunk: direct 64-bit loads (float pair == f32x2 operand)
    ull wr2[RW / 2];
    {
        const ull* wrow = reinterpret_cast<const ull*>(Whh + (size_t)j * HH);
#pragma unroll
        for (int q = 0; q < RW / 2; ++q) wr2[q] = wrow[q];
    }

    const float wi0 = Wih[j * 3 + 0];
    const float wi1 = Wih[j * 3 + 1];
    const float wi2 = Wih[j * 3 + 2];

    // h0 = relu(relu(ones(2) @ W1^T + b1) @ W2^T + b2)  (identical for every batch)
    if (j < 64) {
        float s = b1[j] + W1[j * 2 + 0] + W1[j * 2 + 1];
        hid[j] = fmaxf(s, 0.f);
    }
    __syncthreads();
    {
        float acc = b2[j];
#pragma unroll
        for (int k = 0; k < 64; ++k) acc = fmaf(W2[j * 64 + k], hid[k], acc);
        hbuf[j] = fmaxf(acc, 0.f);
    }
    __syncthreads();

    const float* xb = x + (size_t)b * TT * 3;
    float* pb = p_out + (size_t)b * TT * HH;

    int cur = 0;
    for (int t = 0; t < TT; ++t) {
        const float x0 = __ldg(xb + t * 3 + 0);
        const float x1 = __ldg(xb + t * 3 + 1);
        const float x2 = __ldg(xb + t * 3 + 2);
        const float* hc = hbuf + cur * HH;

        ull a0 = pack2(fmaf(wi0, x0, wi1 * x1), wi2 * x2);
        ull a1 = 0ULL;
        ull a2 = 0ULL;
        ull a3 = 0ULL;

        // register part: k in [0, RW), 4 floats (2 pairs) per iteration
#pragma unroll
        for (int q = 0; q < RW / 4; ++q) {          // 48 iterations
            ulonglong2 h2 = *reinterpret_cast<const ulonglong2*>(hc + 4 * q);
            if (q & 1) { ffma2(a2, wr2[2 * q], h2.x); ffma2(a3, wr2[2 * q + 1], h2.y); }
            else       { ffma2(a0, wr2[2 * q], h2.x); ffma2(a1, wr2[2 * q + 1], h2.y); }
        }
        // SMEM part: k in [RW, 256)
#pragma unroll
        for (int g = 0; g < SW / 4; ++g) {          // 16 iterations
            ulonglong2 w2 = Ws[g * HH + j];
            ulonglong2 h2 = *reinterpret_cast<const ulonglong2*>(hc + RW + 4 * g);
            if (g & 1) { ffma2(a2, w2.x, h2.x); ffma2(a3, w2.y, h2.y); }
            else       { ffma2(a0, w2.x, h2.x); ffma2(a1, w2.y, h2.y); }
        }

        float2 f0 = unpack2(a0), f1 = unpack2(a1), f2 = unpack2(a2), f3 = unpack2(a3);
        const float h = fmaxf(((f0.x + f0.y) + (f1.x + f1.y)) +
                              ((f2.x + f2.y) + (f3.x + f3.y)), 0.f);
        hbuf[(cur ^ 1) * HH + j] = h;
        pb[(size_t)t * HH + j] = h;
        __syncthreads();
        cur ^= 1;
    }
}

// ---------------------------------------------------------------------------
// Squared-norm kernel: one warp per row of p
// ---------------------------------------------------------------------------
__global__ void sq_kernel(const float* __restrict__ p)
{
    const int w = threadIdx.x >> 5;
    const int lane = threadIdx.x & 31;
    const int row = blockIdx.x * 8 + w;
    const float* pr = p + (size_t)row * HH;

    float4 v0 = *reinterpret_cast<const float4*>(pr + lane * 4);
    float4 v1 = *reinterpret_cast<const float4*>(pr + 128 + lane * 4);
    float s = v0.x * v0.x + v0.y * v0.y + v0.z * v0.z + v0.w * v0.w
            + v1.x * v1.x + v1.y * v1.y + v1.z * v1.z + v1.w * v1.w;
#pragma unroll
    for (int o = 16; o > 0; o >>= 1) s += __shfl_xor_sync(0xFFFFFFFFu, s, o);
    if (lane == 0) g_sq[row] = s;
}

// ---------------------------------------------------------------------------
// gram/corr kernel: batched SYRK with fused exp epilogue, FFMA2 inner loop,
// K-chunk = 32 (16 barrier pairs per tile instead of 32).
// Grid (36, 128): 36 upper-triangular 128x128 tile pairs per batch.
// ---------------------------------------------------------------------------
#define KC 32
__global__ void __launch_bounds__(256, 2) gram_kernel(
    const float* __restrict__ p, float* __restrict__ corr)
{
    extern __shared__ float sm[];
    float* As = sm;                  // KC * 132
    float* Bs = sm + KC * 132;       // KC * 132
    float* stage = sm;               // 128 * 132 (reused after mainloop)
    __shared__ float sqa[128], sqb[128];

    const int b = blockIdx.y;
    int pair = blockIdx.x;
    int ti = 0;
    while (pair >= 8 - ti) { pair -= (8 - ti); ++ti; }
    const int tj = ti + pair;
    const int tib = ti * 128;
    const int tjb = tj * 128;

    const int tid = threadIdx.x;
    const int tx = tid & 15;
    const int ty = tid >> 4;

    // sq loads overlap the first chunk staging
    if (tid < 128) sqa[tid] = g_sq[b * TT + tib + tid];
    else           sqb[tid - 128] = g_sq[b * TT + tjb + (tid - 128)];

    const float* pA = p + ((size_t)b * TT + tib) * HH;
    const float* pB = p + ((size_t)b * TT + tjb) * HH;

    ull acc2[8][4];
#pragma unroll
    for (int i = 0; i < 8; ++i)
#pragma unroll
        for (int jj = 0; jj < 4; ++jj) acc2[i][jj] = 0ULL;

    for (int kk = 0; kk < HH; kk += KC) {
        __syncthreads();
#pragma unroll
        for (int v = 0; v < KC / 8; ++v) {
            const int fi = tid + v * 256;      // 0 .. 128*KC/4-1
            const int row = fi >> 3;
            const int kc = (fi & 7) * 4;
            float4 a  = *reinterpret_cast<const float4*>(pA + (size_t)row * HH + kk + kc);
            float4 bv = *reinterpret_cast<const float4*>(pB + (size_t)row * HH + kk + kc);
            As[(kc + 0) * 132 + row] = a.x;
            As[(kc + 1) * 132 + row] = a.y;
            As[(kc + 2) * 132 + row] = a.z;
            As[(kc + 3) * 132 + row] = a.w;
            Bs[(kc + 0) * 132 + row] = bv.x;
            Bs[(kc + 1) * 132 + row] = bv.y;
            Bs[(kc + 2) * 132 + row] = bv.z;
            Bs[(kc + 3) * 132 + row] = bv.w;
        }
        __syncthreads();
#pragma unroll
        for (int k = 0; k < KC; ++k) {
            float4 a0 = *reinterpret_cast<float4*>(&As[k * 132 + ty * 8]);
            float4 a1 = *reinterpret_cast<float4*>(&As[k * 132 + ty * 8 + 4]);
            ulonglong2 b0 = *reinterpret_cast<ulonglong2*>(&Bs[k * 132 + tx * 8]);
            ulonglong2 b1 = *reinterpret_cast<ulonglong2*>(&Bs[k * 132 + tx * 8 + 4]);
            ull ad[8];
            ad[0] = pack2(a0.x, a0.x); ad[1] = pack2(a0.y, a0.y);
            ad[2] = pack2(a0.z, a0.z); ad[3] = pack2(a0.w, a0.w);
            ad[4] = pack2(a1.x, a1.x); ad[5] = pack2(a1.y, a1.y);
            ad[6] = pack2(a1.z, a1.z); ad[7] = pack2(a1.w, a1.w);
            ull bv2[4] = {b0.x, b0.y, b1.x, b1.y};
#pragma unroll
            for (int i = 0; i < 8; ++i)
#pragma unroll
                for (int jj = 0; jj < 4; ++jj)
                    ffma2(acc2[i][jj], ad[i], bv2[jj]);
        }
    }

    __syncthreads();
#pragma unroll
    for (int i = 0; i < 8; ++i) {
        const float si = sqa[ty * 8 + i];
#pragma unroll
        for (int jj = 0; jj < 4; ++jj) {
            float2 c = unpack2(acc2[i][jj]);
            float dp0 = fmaxf(si + sqb[tx * 8 + 2 * jj]     - 2.f * c.x, 0.f);
            float dp1 = fmaxf(si + sqb[tx * 8 + 2 * jj + 1] - 2.f * c.y, 0.f);
            stage[(ty * 8 + i) * 132 + tx * 8 + 2 * jj]     = __expf(-dp0);
            stage[(ty * 8 + i) * 132 + tx * 8 + 2 * jj + 1] = __expf(-dp1);
        }
    }
    __syncthreads();

    float* cb = corr + (size_t)b * TT * TT;
#pragma unroll
    for (int m = 0; m < 16; ++m) {
        const int idx = m * 256 + tid;
        const int row = idx >> 5;
        const int c4 = (idx & 31) * 4;
        float4 v = *reinterpret_cast<float4*>(&stage[row * 132 + c4]);
        *reinterpret_cast<float4*>(cb + (size_t)(tib + row) * TT + tjb + c4) = v;
    }
    if (ti != tj) {
        for (int m = 0; m < 64; ++m) {
            const int idx = m * 256 + tid;
            const int c = idx >> 7;
            const int r = idx & 127;
            cb[(size_t)(tjb + c) * TT + tib + r] = stage[r * 132 + c];
        }
    }
}

// ---------------------------------------------------------------------------
extern "C" void kernel_launch(void* const* d_in, const int* in_sizes, int n_in,
                              void* d_out, int out_size)
{
    const float* x   = (const float*)d_in[0];
    const float* W1  = (const float*)d_in[1];
    const float* b1  = (const float*)d_in[2];
    const float* W2  = (const float*)d_in[3];
    const float* b2  = (const float*)d_in[4];
    const float* Wih = (const float*)d_in[5];
    const float* Whh = (const float*)d_in[6];

    float* out  = (float*)d_out;
    float* corr = out;                                 // [B, T, T]
    float* p    = out + (size_t)BB * TT * TT;          // [B, T, H]

    const size_t rnn_smem  = 576 * sizeof(float) + (size_t)(SW / 4) * HH * sizeof(ulonglong2);
    const size_t gram_smem = (size_t)(128 * 132) * sizeof(float);       // 67.5 KB
    cudaFuncSetAttribute(rnn_kernel,  cudaFuncAttributeMaxDynamicSharedMemorySize, (int)rnn_smem);
    cudaFuncSetAttribute(gram_kernel, cudaFuncAttributeMaxDynamicSharedMemorySize, (int)gram_smem);

    rnn_kernel<<<BB, 256, rnn_smem>>>(x, W1, b1, W2, b2, Wih, Whh, p);
    sq_kernel<<<(BB * TT) / 8, 256>>>(p);
    gram_kernel<<<dim3(36, BB), 256, gram_smem>>>(p, corr);
}

// round 4
// speedup vs baseline: 1.0248x; 1.0248x over previous
#include <cuda_runtime.h>
#include <cstdint>

#define BB 128
#define TT 1024
#define HH 256
#define RW 160           // W_hh columns in registers per thread (80 f32x2 pairs)
#define SW 96            // W_hh columns in shared memory (24 groups of 4)

typedef unsigned long long ull;

// scratch: per-row squared norms of p
__device__ float g_sq[BB * TT];

// ---------------- packed fp32x2 helpers (Blackwell FFMA2) ----------------
__device__ __forceinline__ void ffma2(ull& acc, ull a, ull b) {
    asm("fma.rn.f32x2 %0, %1, %2, %3;" : "=l"(acc) : "l"(a), "l"(b), "l"(acc));
}
__device__ __forceinline__ float2 unpack2(ull v) {
    unsigned lo, hi;
    asm("mov.b64 {%0, %1}, %2;" : "=r"(lo), "=r"(hi) : "l"(v));
    return make_float2(__uint_as_float(lo), __uint_as_float(hi));
}
__device__ __forceinline__ ull pack2(float lo, float hi) {
    ull r;
    asm("mov.b64 %0, {%1, %2};" : "=l"(r) : "r"(__float_as_uint(lo)), "r"(__float_as_uint(hi)));
    return r;
}

// ---------------------------------------------------------------------------
// RNN kernel: one block per batch, thread j owns output neuron j.
// W_hh row j: first RW entries in registers as f32x2 pairs (direct 64-bit
// loads), last SW entries in SMEM as ulonglong2 pairs ([group][j] layout).
// RW=160 keeps ~95 registers free so ptxas can software-pipeline the LDS
// stream (measured best; RW>=192 collapses MLP and regresses).
// ---------------------------------------------------------------------------
__global__ void __launch_bounds__(256, 1) rnn_kernel(
    const float* __restrict__ x,   const float* __restrict__ W1,
    const float* __restrict__ b1,  const float* __restrict__ W2,
    const float* __restrict__ b2,  const float* __restrict__ Wih,
    const float* __restrict__ Whh, float* __restrict__ p_out)
{
    extern __shared__ float sm[];
    float* hbuf = sm;                                  // 2 * 256 (ping-pong h)
    float* hid  = sm + 512;                            // 64
    ulonglong2* Ws = reinterpret_cast<ulonglong2*>(sm + 576);  // (SW/4) * 256 entries

    const int j = threadIdx.x;
    const int b = blockIdx.x;

    // stage SMEM weight chunk: Ws[g*256+j] = Whh[j][RW+4g .. +3]
    for (int g = 0; g < SW / 4; ++g) {
        float4 w = *reinterpret_cast<const float4*>(Whh + (size_t)j * HH + RW + 4 * g);
        Ws[g * HH + j] = *reinterpret_cast<const ulonglong2*>(&w);
    }

    // register weight chunk: direct 64-bit loads (float pair == f32x2 operand)
    ull wr2[RW / 2];
    {
        const ull* wrow = reinterpret_cast<const ull*>(Whh + (size_t)j * HH);
#pragma unroll
        for (int q = 0; q < RW / 2; ++q) wr2[q] = wrow[q];
    }

    const float wi0 = Wih[j * 3 + 0];
    const float wi1 = Wih[j * 3 + 1];
    const float wi2 = Wih[j * 3 + 2];

    // h0 = relu(relu(ones(2) @ W1^T + b1) @ W2^T + b2)  (identical for every batch)
    if (j < 64) {
        float s = b1[j] + W1[j * 2 + 0] + W1[j * 2 + 1];
        hid[j] = fmaxf(s, 0.f);
    }
    __syncthreads();
    {
        float acc = b2[j];
#pragma unroll
        for (int k = 0; k < 64; ++k) acc = fmaf(W2[j * 64 + k], hid[k], acc);
        hbuf[j] = fmaxf(acc, 0.f);
    }
    __syncthreads();

    const float* xb = x + (size_t)b * TT * 3;
    float* pb = p_out + (size_t)b * TT * HH;

    int cur = 0;
    for (int t = 0; t < TT; ++t) {
        const float x0 = __ldg(xb + t * 3 + 0);
        const float x1 = __ldg(xb + t * 3 + 1);
        const float x2 = __ldg(xb + t * 3 + 2);
        const float* hc = hbuf + cur * HH;

        ull a0 = pack2(fmaf(wi0, x0, wi1 * x1), wi2 * x2);
        ull a1 = 0ULL;
        ull a2 = 0ULL;
        ull a3 = 0ULL;

        // register part: k in [0, RW), 4 floats (2 pairs) per iteration
#pragma unroll
        for (int q = 0; q < RW / 4; ++q) {          // 40 iterations
            ulonglong2 h2 = *reinterpret_cast<const ulonglong2*>(hc + 4 * q);
            if (q & 1) { ffma2(a2, wr2[2 * q], h2.x); ffma2(a3, wr2[2 * q + 1], h2.y); }
            else       { ffma2(a0, wr2[2 * q], h2.x); ffma2(a1, wr2[2 * q + 1], h2.y); }
        }
        // SMEM part: k in [RW, 256)
#pragma unroll
        for (int g = 0; g < SW / 4; ++g) {          // 24 iterations
            ulonglong2 w2 = Ws[g * HH + j];
            ulonglong2 h2 = *reinterpret_cast<const ulonglong2*>(hc + RW + 4 * g);
            if (g & 1) { ffma2(a2, w2.x, h2.x); ffma2(a3, w2.y, h2.y); }
            else       { ffma2(a0, w2.x, h2.x); ffma2(a1, w2.y, h2.y); }
        }

        float2 f0 = unpack2(a0), f1 = unpack2(a1), f2 = unpack2(a2), f3 = unpack2(a3);
        const float h = fmaxf(((f0.x + f0.y) + (f1.x + f1.y)) +
                              ((f2.x + f2.y) + (f3.x + f3.y)), 0.f);
        hbuf[(cur ^ 1) * HH + j] = h;
        pb[(size_t)t * HH + j] = h;
        __syncthreads();
        cur ^= 1;
    }
}

// ---------------------------------------------------------------------------
// Squared-norm kernel: one warp per row of p
// ---------------------------------------------------------------------------
__global__ void sq_kernel(const float* __restrict__ p)
{
    const int w = threadIdx.x >> 5;
    const int lane = threadIdx.x & 31;
    const int row = blockIdx.x * 8 + w;
    const float* pr = p + (size_t)row * HH;

    float4 v0 = *reinterpret_cast<const float4*>(pr + lane * 4);
    float4 v1 = *reinterpret_cast<const float4*>(pr + 128 + lane * 4);
    float s = v0.x * v0.x + v0.y * v0.y + v0.z * v0.z + v0.w * v0.w
            + v1.x * v1.x + v1.y * v1.y + v1.z * v1.z + v1.w * v1.w;
#pragma unroll
    for (int o = 16; o > 0; o >>= 1) s += __shfl_xor_sync(0xFFFFFFFFu, s, o);
    if (lane == 0) g_sq[row] = s;
}

// ---------------------------------------------------------------------------
// gram/corr kernel: batched SYRK with fused exp epilogue, FFMA2 inner loop.
// KC=16 (the measured-best R2 configuration).
// Grid (36, 128): 36 upper-triangular 128x128 tile pairs per batch.
// ---------------------------------------------------------------------------
__global__ void __launch_bounds__(256, 2) gram_kernel(
    const float* __restrict__ p, float* __restrict__ corr)
{
    extern __shared__ float sm[];
    float* As = sm;                  // 16 * 132
    float* Bs = sm + 16 * 132;       // 16 * 132
    float* stage = sm;               // 128 * 132 (reused after mainloop)
    __shared__ float sqa[128], sqb[128];

    const int b = blockIdx.y;
    int pair = blockIdx.x;
    int ti = 0;
    while (pair >= 8 - ti) { pair -= (8 - ti); ++ti; }
    const int tj = ti + pair;
    const int tib = ti * 128;
    const int tjb = tj * 128;

    const int tid = threadIdx.x;
    const int tx = tid & 15;
    const int ty = tid >> 4;

    // sq loads overlap the first chunk staging
    if (tid < 128) sqa[tid] = g_sq[b * TT + tib + tid];
    else           sqb[tid - 128] = g_sq[b * TT + tjb + (tid - 128)];

    const float* pA = p + ((size_t)b * TT + tib) * HH;
    const float* pB = p + ((size_t)b * TT + tjb) * HH;

    ull acc2[8][4];
#pragma unroll
    for (int i = 0; i < 8; ++i)
#pragma unroll
        for (int jj = 0; jj < 4; ++jj) acc2[i][jj] = 0ULL;

    for (int kk = 0; kk < HH; kk += 16) {
        __syncthreads();
#pragma unroll
        for (int v = 0; v < 2; ++v) {
            const int fi = tid + v * 256;      // 0..511
            const int row = fi >> 2;
            const int kc = (fi & 3) * 4;
            float4 a  = *reinterpret_cast<const float4*>(pA + (size_t)row * HH + kk + kc);
            float4 bv = *reinterpret_cast<const float4*>(pB + (size_t)row * HH + kk + kc);
            As[(kc + 0) * 132 + row] = a.x;
            As[(kc + 1) * 132 + row] = a.y;
            As[(kc + 2) * 132 + row] = a.z;
            As[(kc + 3) * 132 + row] = a.w;
            Bs[(kc + 0) * 132 + row] = bv.x;
            Bs[(kc + 1) * 132 + row] = bv.y;
            Bs[(kc + 2) * 132 + row] = bv.z;
            Bs[(kc + 3) * 132 + row] = bv.w;
        }
        __syncthreads();
#pragma unroll
        for (int k = 0; k < 16; ++k) {
            float4 a0 = *reinterpret_cast<float4*>(&As[k * 132 + ty * 8]);
            float4 a1 = *reinterpret_cast<float4*>(&As[k * 132 + ty * 8 + 4]);
            ulonglong2 b0 = *reinterpret_cast<ulonglong2*>(&Bs[k * 132 + tx * 8]);
            ulonglong2 b1 = *reinterpret_cast<ulonglong2*>(&Bs[k * 132 + tx * 8 + 4]);
            ull ad[8];
            ad[0] = pack2(a0.x, a0.x); ad[1] = pack2(a0.y, a0.y);
            ad[2] = pack2(a0.z, a0.z); ad[3] = pack2(a0.w, a0.w);
            ad[4] = pack2(a1.x, a1.x); ad[5] = pack2(a1.y, a1.y);
            ad[6] = pack2(a1.z, a1.z); ad[7] = pack2(a1.w, a1.w);
            ull bv2[4] = {b0.x, b0.y, b1.x, b1.y};
#pragma unroll
            for (int i = 0; i < 8; ++i)
#pragma unroll
                for (int jj = 0; jj < 4; ++jj)
                    ffma2(acc2[i][jj], ad[i], bv2[jj]);
        }
    }

    __syncthreads();
#pragma unroll
    for (int i = 0; i < 8; ++i) {
        const float si = sqa[ty * 8 + i];
#pragma unroll
        for (int jj = 0; jj < 4; ++jj) {
            float2 c = unpack2(acc2[i][jj]);
            float dp0 = fmaxf(si + sqb[tx * 8 + 2 * jj]     - 2.f * c.x, 0.f);
            float dp1 = fmaxf(si + sqb[tx * 8 + 2 * jj + 1] - 2.f * c.y, 0.f);
            stage[(ty * 8 + i) * 132 + tx * 8 + 2 * jj]     = __expf(-dp0);
            stage[(ty * 8 + i) * 132 + tx * 8 + 2 * jj + 1] = __expf(-dp1);
        }
    }
    __syncthreads();

    float* cb = corr + (size_t)b * TT * TT;
#pragma unroll
    for (int m = 0; m < 16; ++m) {
        const int idx = m * 256 + tid;
        const int row = idx >> 5;
        const int c4 = (idx & 31) * 4;
        float4 v = *reinterpret_cast<float4*>(&stage[row * 132 + c4]);
        *reinterpret_cast<float4*>(cb + (size_t)(tib + row) * TT + tjb + c4) = v;
    }
    if (ti != tj) {
        for (int m = 0; m < 64; ++m) {
            const int idx = m * 256 + tid;
            const int c = idx >> 7;
            const int r = idx & 127;
            cb[(size_t)(tjb + c) * TT + tib + r] = stage[r * 132 + c];
        }
    }
}

// ---------------------------------------------------------------------------
extern "C" void kernel_launch(void* const* d_in, const int* in_sizes, int n_in,
                              void* d_out, int out_size)
{
    const float* x   = (const float*)d_in[0];
    const float* W1  = (const float*)d_in[1];
    const float* b1  = (const float*)d_in[2];
    const float* W2  = (const float*)d_in[3];
    const float* b2  = (const float*)d_in[4];
    const float* Wih = (const float*)d_in[5];
    const float* Whh = (const float*)d_in[6];

    float* out  = (float*)d_out;
    float* corr = out;                                 // [B, T, T]
    float* p    = out + (size_t)BB * TT * TT;          // [B, T, H]

    const size_t rnn_smem  = 576 * sizeof(float) + (size_t)(SW / 4) * HH * sizeof(ulonglong2);
    const size_t gram_smem = (size_t)(128 * 132) * sizeof(float);       // 67.5 KB
    cudaFuncSetAttribute(rnn_kernel,  cudaFuncAttributeMaxDynamicSharedMemorySize, (int)rnn_smem);
    cudaFuncSetAttribute(gram_kernel, cudaFuncAttributeMaxDynamicSharedMemorySize, (int)gram_smem);

    rnn_kernel<<<BB, 256, rnn_smem>>>(x, W1, b1, W2, b2, Wih, Whh, p);
    sq_kernel<<<(BB * TT) / 8, 256>>>(p);
    gram_kernel<<<dim3(36, BB), 256, gram_smem>>>(p, corr);
}

// round 6
// speedup vs baseline: 1.1985x; 1.1695x over previous
#include <cuda_runtime.h>
#include <cuda_bf16.h>
#include <cstdint>

#define BB 128
#define TT 1024
#define HH 256
#define RW 160           // RNN: W_hh columns in registers (measured-best split)
#define SW 96            // RNN: W_hh columns in shared memory

// scratch: per-row squared norms of p
__device__ float g_sq[BB * TT];

// ======================= warp-MMA helpers (base-PTX, sm_80+) ================
__device__ __forceinline__ uint32_t smem_u32(const void* p) {
    uint32_t a;
    asm("{ .reg .u64 t; cvta.to.shared.u64 t, %1; cvt.u32.u64 %0, t; }" : "=r"(a) : "l"(p));
    return a;
}
__device__ __forceinline__ void ldsm4(uint32_t& r0, uint32_t& r1, uint32_t& r2, uint32_t& r3,
                                      uint32_t addr) {
    asm volatile("ldmatrix.sync.aligned.m8n8.x4.shared.b16 {%0,%1,%2,%3}, [%4];"
                 : "=r"(r0), "=r"(r1), "=r"(r2), "=r"(r3) : "r"(addr));
}
__device__ __forceinline__ void mma16816(float* d, const uint32_t* a, uint32_t b0, uint32_t b1) {
    asm volatile("mma.sync.aligned.m16n8k16.row.col.f32.bf16.bf16.f32 "
                 "{%0,%1,%2,%3},{%4,%5,%6,%7},{%8,%9},{%0,%1,%2,%3};"
                 : "+f"(d[0]), "+f"(d[1]), "+f"(d[2]), "+f"(d[3])
                 : "r"(a[0]), "r"(a[1]), "r"(a[2]), "r"(a[3]), "r"(b0), "r"(b1));
}
__device__ __forceinline__ unsigned b2u(__nv_bfloat162 v) {
    return *reinterpret_cast<unsigned*>(&v);
}
__device__ __forceinline__ int swz(int off) { return off ^ ((off >> 3) & 0x70); }

// ---------------------------------------------------------------------------
// RNN kernel (R1 scalar version — measured best): one block per batch,
// thread j owns output neuron j.
// ---------------------------------------------------------------------------
__global__ void __launch_bounds__(256, 1) rnn_kernel(
    const float* __restrict__ x,   const float* __restrict__ W1,
    const float* __restrict__ b1,  const float* __restrict__ W2,
    const float* __restrict__ b2,  const float* __restrict__ Wih,
    const float* __restrict__ Whh, float* __restrict__ p_out)
{
    extern __shared__ float sm[];
    float* hbuf = sm;            // 2 * 256 (ping-pong h)
    float* hid  = sm + 512;      // 64
    float* Ws   = sm + 576;      // SW * 256

    const int j = threadIdx.x;
    const int b = blockIdx.x;

    for (int k = 0; k < SW; ++k)
        Ws[k * HH + j] = Whh[j * HH + RW + k];

    float wr[RW];
#pragma unroll
    for (int k = 0; k < RW; ++k) wr[k] = Whh[j * HH + k];

    const float wi0 = Wih[j * 3 + 0];
    const float wi1 = Wih[j * 3 + 1];
    const float wi2 = Wih[j * 3 + 2];

    if (j < 64) {
        float s = b1[j] + W1[j * 2 + 0] + W1[j * 2 + 1];
        hid[j] = fmaxf(s, 0.f);
    }
    __syncthreads();
    {
        float acc = b2[j];
#pragma unroll
        for (int k = 0; k < 64; ++k) acc = fmaf(W2[j * 64 + k], hid[k], acc);
        hbuf[j] = fmaxf(acc, 0.f);
    }
    __syncthreads();

    const float* xb = x + (size_t)b * TT * 3;
    float* pb = p_out + (size_t)b * TT * HH;

    int cur = 0;
    for (int t = 0; t < TT; ++t) {
        const float x0 = __ldg(xb + t * 3 + 0);
        const float x1 = __ldg(xb + t * 3 + 1);
        const float x2 = __ldg(xb + t * 3 + 2);
        const float* hc = hbuf + cur * HH;

        float a0 = wi0 * x0;
        float a1 = wi1 * x1;
        float a2 = wi2 * x2;
        float a3 = 0.f;

#pragma unroll
        for (int k = 0; k < RW; k += 4) {
            float4 h4 = *reinterpret_cast<const float4*>(hc + k);
            a0 = fmaf(wr[k + 0], h4.x, a0);
            a1 = fmaf(wr[k + 1], h4.y, a1);
            a2 = fmaf(wr[k + 2], h4.z, a2);
            a3 = fmaf(wr[k + 3], h4.w, a3);
        }
#pragma unroll
        for (int k = 0; k < SW; k += 4) {
            float4 h4 = *reinterpret_cast<const float4*>(hc + RW + k);
            a0 = fmaf(Ws[(k + 0) * HH + j], h4.x, a0);
            a1 = fmaf(Ws[(k + 1) * HH + j], h4.y, a1);
            a2 = fmaf(Ws[(k + 2) * HH + j], h4.z, a2);
            a3 = fmaf(Ws[(k + 3) * HH + j], h4.w, a3);
        }

        const float h = fmaxf((a0 + a1) + (a2 + a3), 0.f);
        hbuf[(cur ^ 1) * HH + j] = h;
        pb[(size_t)t * HH + j] = h;
        __syncthreads();
        cur ^= 1;
    }
}

// ---------------------------------------------------------------------------
// Squared-norm kernel: one warp per row of p
// ---------------------------------------------------------------------------
__global__ void sq_kernel(const float* __restrict__ p)
{
    const int w = threadIdx.x >> 5;
    const int lane = threadIdx.x & 31;
    const int row = blockIdx.x * 8 + w;
    const float* pr = p + (size_t)row * HH;

    float4 v0 = *reinterpret_cast<const float4*>(pr + lane * 4);
    float4 v1 = *reinterpret_cast<const float4*>(pr + 128 + lane * 4);
    float s = v0.x * v0.x + v0.y * v0.y + v0.z * v0.z + v0.w * v0.w
            + v1.x * v1.x + v1.y * v1.y + v1.z * v1.z + v1.w * v1.w;
#pragma unroll
    for (int o = 16; o > 0; o >>= 1) s += __shfl_xor_sync(0xFFFFFFFFu, s, o);
    if (lane == 0) g_sq[row] = s;
}

// ---------------------------------------------------------------------------
// Tensor-core gram kernel (mma.sync bf16x3 split), fused exp epilogue.
// CTA = one 128x128 upper-triangular tile pair. 8 warps in 2(m) x 4(n).
// K = 256 in 4 chunks of 64. hi/lo bf16 tiles in xor-swizzled SMEM,
// k-contiguous rows -> non-transposed ldmatrix for both A and B.
// D += Ahi*Bhi + Ahi*Blo + Alo*Bhi in fp32 fragments.
// ---------------------------------------------------------------------------
#define GT_AHI 0
#define GT_ALO 16384
#define GT_BHI 32768
#define GT_BLO 49152
#define GT_SMEM 69632      // >= max(4*16KB tiles, 128*132*4 stage)

__device__ __forceinline__ void stage_bf16(const float* __restrict__ src, int kk,
                                           char* __restrict__ hi, char* __restrict__ lo,
                                           int tid)
{
#pragma unroll
    for (int m = 0; m < 4; ++m) {
        const int g = m * 256 + tid;        // 0..1023 : 128 rows x 8 half8-groups
        const int row = g >> 3;
        const int k8 = (g & 7) * 8;         // halves within chunk
        const float* s = src + (size_t)row * HH + kk + k8;
        float4 v0 = *reinterpret_cast<const float4*>(s);
        float4 v1 = *reinterpret_cast<const float4*>(s + 4);

        __nv_bfloat16 h0 = __float2bfloat16(v0.x), h1 = __float2bfloat16(v0.y);
        __nv_bfloat16 h2 = __float2bfloat16(v0.z), h3 = __float2bfloat16(v0.w);
        __nv_bfloat16 h4 = __float2bfloat16(v1.x), h5 = __float2bfloat16(v1.y);
        __nv_bfloat16 h6 = __float2bfloat16(v1.z), h7 = __float2bfloat16(v1.w);
        uint4 hp = make_uint4(
            b2u(__halves2bfloat162(h0, h1)), b2u(__halves2bfloat162(h2, h3)),
            b2u(__halves2bfloat162(h4, h5)), b2u(__halves2bfloat162(h6, h7)));
        uint4 lp = make_uint4(
            b2u(__halves2bfloat162(__float2bfloat16(v0.x - __bfloat162float(h0)),
                                   __float2bfloat16(v0.y - __bfloat162float(h1)))),
            b2u(__halves2bfloat162(__float2bfloat16(v0.z - __bfloat162float(h2)),
                                   __float2bfloat16(v0.w - __bfloat162float(h3)))),
            b2u(__halves2bfloat162(__float2bfloat16(v1.x - __bfloat162float(h4)),
                                   __float2bfloat16(v1.y - __bfloat162float(h5)))),
            b2u(__halves2bfloat162(__float2bfloat16(v1.z - __bfloat162float(h6)),
                                   __float2bfloat16(v1.w - __bfloat162float(h7)))));
        const int off = swz(row * 128 + k8 * 2);
        *reinterpret_cast<uint4*>(hi + off) = hp;
        *reinterpret_cast<uint4*>(lo + off) = lp;
    }
}

__global__ void __launch_bounds__(256, 1) gram_mma_kernel(
    const float* __restrict__ p, float* __restrict__ corr)
{
    extern __shared__ char smc[];
    float* stage = reinterpret_cast<float*>(smc);    // reused after mainloop
    __shared__ float sqa[128], sqb[128];

    const uint32_t sbase = smem_u32(smc);
    const int tid = threadIdx.x;
    const int wid = tid >> 5;
    const int lane = tid & 31;
    const int warp_m = wid >> 2;       // 0..1
    const int warp_n = wid & 3;        // 0..3

    const int b = blockIdx.y;
    int pair = blockIdx.x;
    int ti = 0;
    while (pair >= 8 - ti) { pair -= (8 - ti); ++ti; }
    const int tj = ti + pair;
    const int tib = ti * 128;
    const int tjb = tj * 128;

    if (tid < 128) sqa[tid] = g_sq[b * TT + tib + tid];
    else           sqb[tid - 128] = g_sq[b * TT + tjb + (tid - 128)];

    const float* pA = p + ((size_t)b * TT + tib) * HH;
    const float* pB = p + ((size_t)b * TT + tjb) * HH;

    // per-lane ldmatrix row/k components (canonical x4 tile ordering)
    const int a_row = warp_m * 64 + (lane & 7) + ((lane >> 3) & 1) * 8;  // + mt*16
    const int a_k8  = ((lane >> 4) & 1) * 8;                             // + ks*16
    const int b_row = warp_n * 32 + (lane & 7) + ((lane >> 4) & 1) * 8;  // + nt2*16
    const int b_k8  = ((lane >> 3) & 1) * 8;                             // + ks*16

    float acc[4][4][4];
#pragma unroll
    for (int i = 0; i < 4; ++i)
#pragma unroll
        for (int jj = 0; jj < 4; ++jj)
#pragma unroll
            for (int f = 0; f < 4; ++f) acc[i][jj][f] = 0.f;

    for (int chunk = 0; chunk < 4; ++chunk) {
        const int kk = chunk * 64;
        __syncthreads();
        stage_bf16(pA, kk, smc + GT_AHI, smc + GT_ALO, tid);
        stage_bf16(pB, kk, smc + GT_BHI, smc + GT_BLO, tid);
        __syncthreads();

#pragma unroll
        for (int ks = 0; ks < 4; ++ks) {
            // B fragments: 4 n8-tiles, hi & lo
            uint32_t bh[8], bl[8];
#pragma unroll
            for (int nt2 = 0; nt2 < 2; ++nt2) {
                const int off = swz((b_row + nt2 * 16) * 128 + (ks * 16 + b_k8) * 2);
                ldsm4(bh[nt2 * 4 + 0], bh[nt2 * 4 + 1], bh[nt2 * 4 + 2], bh[nt2 * 4 + 3],
                      sbase + GT_BHI + off);
                ldsm4(bl[nt2 * 4 + 0], bl[nt2 * 4 + 1], bl[nt2 * 4 + 2], bl[nt2 * 4 + 3],
                      sbase + GT_BLO + off);
            }
#pragma unroll
            for (int mt = 0; mt < 4; ++mt) {
                const int off = swz((a_row + mt * 16) * 128 + (ks * 16 + a_k8) * 2);
                uint32_t ah[4], al[4];
                ldsm4(ah[0], ah[1], ah[2], ah[3], sbase + GT_AHI + off);
                ldsm4(al[0], al[1], al[2], al[3], sbase + GT_ALO + off);
#pragma unroll
                for (int nt = 0; nt < 4; ++nt) {
                    mma16816(acc[mt][nt], ah, bh[nt * 2 + 0], bh[nt * 2 + 1]);
                    mma16816(acc[mt][nt], ah, bl[nt * 2 + 0], bl[nt * 2 + 1]);
                    mma16816(acc[mt][nt], al, bh[nt * 2 + 0], bh[nt * 2 + 1]);
                }
            }
        }
    }

    __syncthreads();   // tiles dead; stage may be written

    // epilogue: fragment -> fused exp -> stage SMEM
#pragma unroll
    for (int mt = 0; mt < 4; ++mt) {
        const int r0 = warp_m * 64 + mt * 16 + (lane >> 2);
        const int r1 = r0 + 8;
        const float s0 = sqa[r0], s1 = sqa[r1];
#pragma unroll
        for (int nt = 0; nt < 4; ++nt) {
            const int c = warp_n * 32 + nt * 8 + 2 * (lane & 3);
            const float q0 = sqb[c], q1 = sqb[c + 1];
            const float* d = acc[mt][nt];
            stage[r0 * 132 + c]     = __expf(-fmaxf(s0 + q0 - 2.f * d[0], 0.f));
            stage[r0 * 132 + c + 1] = __expf(-fmaxf(s0 + q1 - 2.f * d[1], 0.f));
            stage[r1 * 132 + c]     = __expf(-fmaxf(s1 + q0 - 2.f * d[2], 0.f));
            stage[r1 * 132 + c + 1] = __expf(-fmaxf(s1 + q1 - 2.f * d[3], 0.f));
        }
    }
    __syncthreads();

    float* cb = corr + (size_t)b * TT * TT;
#pragma unroll
    for (int m = 0; m < 16; ++m) {
        const int idx = m * 256 + tid;
        const int row = idx >> 5;
        const int c4 = (idx & 31) * 4;
        float4 v = *reinterpret_cast<float4*>(&stage[row * 132 + c4]);
        *reinterpret_cast<float4*>(cb + (size_t)(tib + row) * TT + tjb + c4) = v;
    }
    if (ti != tj) {
        for (int m = 0; m < 64; ++m) {
            const int idx = m * 256 + tid;
            const int c = idx >> 7;
            const int r = idx & 127;
            cb[(size_t)(tjb + c) * TT + tib + r] = stage[r * 132 + c];
        }
    }
}

// ---------------------------------------------------------------------------
extern "C" void kernel_launch(void* const* d_in, const int* in_sizes, int n_in,
                              void* d_out, int out_size)
{
    const float* x   = (const float*)d_in[0];
    const float* W1  = (const float*)d_in[1];
    const float* b1  = (const float*)d_in[2];
    const float* W2  = (const float*)d_in[3];
    const float* b2  = (const float*)d_in[4];
    const float* Wih = (const float*)d_in[5];
    const float* Whh = (const float*)d_in[6];

    float* out  = (float*)d_out;
    float* corr = out;                                 // [B, T, T]
    float* p    = out + (size_t)BB * TT * TT;          // [B, T, H]

    const size_t rnn_smem = (size_t)(576 + SW * HH) * sizeof(float);   // ~98.3 KB
    cudaFuncSetAttribute(rnn_kernel,      cudaFuncAttributeMaxDynamicSharedMemorySize, (int)rnn_smem);
    cudaFuncSetAttribute(gram_mma_kernel, cudaFuncAttributeMaxDynamicSharedMemorySize, GT_SMEM);

    rnn_kernel<<<BB, 256, rnn_smem>>>(x, W1, b1, W2, b2, Wih, Whh, p);
    sq_kernel<<<(BB * TT) / 8, 256>>>(p);
    gram_mma_kernel<<<dim3(36, BB), 256, GT_SMEM>>>(p, corr);
}

// round 7
// speedup vs baseline: 1.3566x; 1.1320x over previous
#include <cuda_runtime.h>
#include <cuda_bf16.h>
#include <cstdint>

#define BB 128
#define TT 1024
#define HH 256
#define RW 160           // RNN: W_hh columns in registers (measured-best split)
#define SW 96            // RNN: W_hh columns in shared memory

// scratch: per-row squared norms + precomputed bf16 hi/lo split of p
__device__ float g_sq[BB * TT];
__device__ __nv_bfloat16 g_phi[(size_t)BB * TT * HH];
__device__ __nv_bfloat16 g_plo[(size_t)BB * TT * HH];

// ======================= warp-MMA helpers (base-PTX, sm_80+) ================
__device__ __forceinline__ uint32_t smem_u32(const void* p) {
    uint32_t a;
    asm("{ .reg .u64 t; cvta.to.shared.u64 t, %1; cvt.u32.u64 %0, t; }" : "=r"(a) : "l"(p));
    return a;
}
__device__ __forceinline__ void ldsm4(uint32_t& r0, uint32_t& r1, uint32_t& r2, uint32_t& r3,
                                      uint32_t addr) {
    asm volatile("ldmatrix.sync.aligned.m8n8.x4.shared.b16 {%0,%1,%2,%3}, [%4];"
                 : "=r"(r0), "=r"(r1), "=r"(r2), "=r"(r3) : "r"(addr));
}
__device__ __forceinline__ void mma16816(float* d, const uint32_t* a, uint32_t b0, uint32_t b1) {
    asm volatile("mma.sync.aligned.m16n8k16.row.col.f32.bf16.bf16.f32 "
                 "{%0,%1,%2,%3},{%4,%5,%6,%7},{%8,%9},{%0,%1,%2,%3};"
                 : "+f"(d[0]), "+f"(d[1]), "+f"(d[2]), "+f"(d[3])
                 : "r"(a[0]), "r"(a[1]), "r"(a[2]), "r"(a[3]), "r"(b0), "r"(b1));
}
__device__ __forceinline__ unsigned b2u(__nv_bfloat162 v) {
    return *reinterpret_cast<unsigned*>(&v);
}
__device__ __forceinline__ int swz(int off) { return off ^ ((off >> 3) & 0x70); }

__device__ __forceinline__ void cpa16(uint32_t dst, const void* src) {
    asm volatile("cp.async.cg.shared.global [%0], [%1], 16;" :: "r"(dst), "l"(src));
}
#define CP_COMMIT() asm volatile("cp.async.commit_group;" ::: "memory")
#define CP_WAIT(n)  asm volatile("cp.async.wait_group %0;" :: "n"(n) : "memory")

// ---------------------------------------------------------------------------
// RNN kernel (scalar, measured best): one block per batch, thread j = neuron j
// ---------------------------------------------------------------------------
__global__ void __launch_bounds__(256, 1) rnn_kernel(
    const float* __restrict__ x,   const float* __restrict__ W1,
    const float* __restrict__ b1,  const float* __restrict__ W2,
    const float* __restrict__ b2,  const float* __restrict__ Wih,
    const float* __restrict__ Whh, float* __restrict__ p_out)
{
    extern __shared__ float sm[];
    float* hbuf = sm;            // 2 * 256 (ping-pong h)
    float* hid  = sm + 512;      // 64
    float* Ws   = sm + 576;      // SW * 256

    const int j = threadIdx.x;
    const int b = blockIdx.x;

    for (int k = 0; k < SW; ++k)
        Ws[k * HH + j] = Whh[j * HH + RW + k];

    float wr[RW];
#pragma unroll
    for (int k = 0; k < RW; ++k) wr[k] = Whh[j * HH + k];

    const float wi0 = Wih[j * 3 + 0];
    const float wi1 = Wih[j * 3 + 1];
    const float wi2 = Wih[j * 3 + 2];

    if (j < 64) {
        float s = b1[j] + W1[j * 2 + 0] + W1[j * 2 + 1];
        hid[j] = fmaxf(s, 0.f);
    }
    __syncthreads();
    {
        float acc = b2[j];
#pragma unroll
        for (int k = 0; k < 64; ++k) acc = fmaf(W2[j * 64 + k], hid[k], acc);
        hbuf[j] = fmaxf(acc, 0.f);
    }
    __syncthreads();

    const float* xb = x + (size_t)b * TT * 3;
    float* pb = p_out + (size_t)b * TT * HH;

    int cur = 0;
    for (int t = 0; t < TT; ++t) {
        const float x0 = __ldg(xb + t * 3 + 0);
        const float x1 = __ldg(xb + t * 3 + 1);
        const float x2 = __ldg(xb + t * 3 + 2);
        const float* hc = hbuf + cur * HH;

        float a0 = wi0 * x0;
        float a1 = wi1 * x1;
        float a2 = wi2 * x2;
        float a3 = 0.f;

#pragma unroll
        for (int k = 0; k < RW; k += 4) {
            float4 h4 = *reinterpret_cast<const float4*>(hc + k);
            a0 = fmaf(wr[k + 0], h4.x, a0);
            a1 = fmaf(wr[k + 1], h4.y, a1);
            a2 = fmaf(wr[k + 2], h4.z, a2);
            a3 = fmaf(wr[k + 3], h4.w, a3);
        }
#pragma unroll
        for (int k = 0; k < SW; k += 4) {
            float4 h4 = *reinterpret_cast<const float4*>(hc + RW + k);
            a0 = fmaf(Ws[(k + 0) * HH + j], h4.x, a0);
            a1 = fmaf(Ws[(k + 1) * HH + j], h4.y, a1);
            a2 = fmaf(Ws[(k + 2) * HH + j], h4.z, a2);
            a3 = fmaf(Ws[(k + 3) * HH + j], h4.w, a3);
        }

        const float h = fmaxf((a0 + a1) + (a2 + a3), 0.f);
        hbuf[(cur ^ 1) * HH + j] = h;
        pb[(size_t)t * HH + j] = h;
        __syncthreads();
        cur ^= 1;
    }
}

// ---------------------------------------------------------------------------
// Prep kernel: per-row squared norm + hi/lo bf16 split of p (written once).
// One warp per row; each lane owns 8 elements (two float4 groups).
// ---------------------------------------------------------------------------
__global__ void prep_kernel(const float* __restrict__ p)
{
    const int w = threadIdx.x >> 5;
    const int lane = threadIdx.x & 31;
    const int row = blockIdx.x * 8 + w;
    const float* pr = p + (size_t)row * HH;

    float4 v0 = *reinterpret_cast<const float4*>(pr + lane * 4);
    float4 v1 = *reinterpret_cast<const float4*>(pr + 128 + lane * 4);

    float s = v0.x * v0.x + v0.y * v0.y + v0.z * v0.z + v0.w * v0.w
            + v1.x * v1.x + v1.y * v1.y + v1.z * v1.z + v1.w * v1.w;
#pragma unroll
    for (int o = 16; o > 0; o >>= 1) s += __shfl_xor_sync(0xFFFFFFFFu, s, o);
    if (lane == 0) g_sq[row] = s;

    __nv_bfloat16* phi = g_phi + (size_t)row * HH;
    __nv_bfloat16* plo = g_plo + (size_t)row * HH;
#pragma unroll
    for (int half = 0; half < 2; ++half) {
        const float4 v = half ? v1 : v0;
        const int c = half * 128 + lane * 4;
        __nv_bfloat16 h0 = __float2bfloat16(v.x), h1 = __float2bfloat16(v.y);
        __nv_bfloat16 h2 = __float2bfloat16(v.z), h3 = __float2bfloat16(v.w);
        uint2 hp = make_uint2(b2u(__halves2bfloat162(h0, h1)),
                              b2u(__halves2bfloat162(h2, h3)));
        uint2 lp = make_uint2(
            b2u(__halves2bfloat162(__float2bfloat16(v.x - __bfloat162float(h0)),
                                   __float2bfloat16(v.y - __bfloat162float(h1)))),
            b2u(__halves2bfloat162(__float2bfloat16(v.z - __bfloat162float(h2)),
                                   __float2bfloat16(v.w - __bfloat162float(h3)))));
        *reinterpret_cast<uint2*>(phi + c) = hp;
        *reinterpret_cast<uint2*>(plo + c) = lp;
    }
}

// ---------------------------------------------------------------------------
// Tensor-core gram kernel (mma.sync bf16x3), cp.async double-buffered staging.
// CTA = one 128x128 upper-triangular tile pair. 8 warps in 2(m) x 4(n).
// K = 256 in 4 chunks of 64 halves (128B rows, proven swizzle layout).
// SMEM: 2 stages x 4 tiles (Ahi,Alo,Bhi,Blo) x 16KB = 128KB.
// ---------------------------------------------------------------------------
#define GT_STAGE 65536
#define GT_TILE  16384
#define GT_SMEM  131072

__device__ __forceinline__ void issue_chunk(
    const __nv_bfloat16* __restrict__ phiA, const __nv_bfloat16* __restrict__ ploA,
    const __nv_bfloat16* __restrict__ phiB, const __nv_bfloat16* __restrict__ ploB,
    int kk, uint32_t sdst, int tid)
{
#pragma unroll
    for (int m = 0; m < 4; ++m) {
        const int g = m * 256 + tid;        // 0..1023 : 128 rows x 8 x 16B
        const int row = g >> 3;
        const int k8 = (g & 7) * 8;
        const int off = swz(row * 128 + k8 * 2);
        const size_t gsrc = (size_t)row * HH + kk + k8;
        cpa16(sdst + 0 * GT_TILE + off, phiA + gsrc);
        cpa16(sdst + 1 * GT_TILE + off, ploA + gsrc);
        cpa16(sdst + 2 * GT_TILE + off, phiB + gsrc);
        cpa16(sdst + 3 * GT_TILE + off, ploB + gsrc);
    }
}

__global__ void __launch_bounds__(256, 1) gram_mma_kernel(float* __restrict__ corr)
{
    extern __shared__ char smc[];
    float* stage = reinterpret_cast<float*>(smc);    // reused after mainloop
    __shared__ float sqa[128], sqb[128];

    const uint32_t sbase = smem_u32(smc);
    const int tid = threadIdx.x;
    const int wid = tid >> 5;
    const int lane = tid & 31;
    const int warp_m = wid >> 2;       // 0..1
    const int warp_n = wid & 3;        // 0..3

    const int b = blockIdx.y;
    int pair = blockIdx.x;
    int ti = 0;
    while (pair >= 8 - ti) { pair -= (8 - ti); ++ti; }
    const int tj = ti + pair;
    const int tib = ti * 128;
    const int tjb = tj * 128;

    if (tid < 128) sqa[tid] = g_sq[b * TT + tib + tid];
    else           sqb[tid - 128] = g_sq[b * TT + tjb + (tid - 128)];

    const __nv_bfloat16* phiA = g_phi + ((size_t)b * TT + tib) * HH;
    const __nv_bfloat16* ploA = g_plo + ((size_t)b * TT + tib) * HH;
    const __nv_bfloat16* phiB = g_phi + ((size_t)b * TT + tjb) * HH;
    const __nv_bfloat16* ploB = g_plo + ((size_t)b * TT + tjb) * HH;

    // per-lane ldmatrix row/k components (canonical x4 tile ordering)
    const int a_row = warp_m * 64 + (lane & 7) + ((lane >> 3) & 1) * 8;  // + mt*16
    const int a_k8  = ((lane >> 4) & 1) * 8;                             // + ks*16
    const int b_row = warp_n * 32 + (lane & 7) + ((lane >> 4) & 1) * 8;  // + nt2*16
    const int b_k8  = ((lane >> 3) & 1) * 8;                             // + ks*16

    float acc[4][4][4];
#pragma unroll
    for (int i = 0; i < 4; ++i)
#pragma unroll
        for (int jj = 0; jj < 4; ++jj)
#pragma unroll
            for (int f = 0; f < 4; ++f) acc[i][jj][f] = 0.f;

    issue_chunk(phiA, ploA, phiB, ploB, 0, sbase, tid);
    CP_COMMIT();

#pragma unroll
    for (int chunk = 0; chunk < 4; ++chunk) {
        if (chunk < 3) {
            issue_chunk(phiA, ploA, phiB, ploB, (chunk + 1) * 64,
                        sbase + ((chunk + 1) & 1) * GT_STAGE, tid);
            CP_COMMIT();
            CP_WAIT(1);
        } else {
            CP_WAIT(0);
        }
        __syncthreads();

        const uint32_t st = sbase + (chunk & 1) * GT_STAGE;
#pragma unroll
        for (int ks = 0; ks < 4; ++ks) {
            uint32_t bh[8], bl[8];
#pragma unroll
            for (int nt2 = 0; nt2 < 2; ++nt2) {
                const int off = swz((b_row + nt2 * 16) * 128 + (ks * 16 + b_k8) * 2);
                ldsm4(bh[nt2 * 4 + 0], bh[nt2 * 4 + 1], bh[nt2 * 4 + 2], bh[nt2 * 4 + 3],
                      st + 2 * GT_TILE + off);
                ldsm4(bl[nt2 * 4 + 0], bl[nt2 * 4 + 1], bl[nt2 * 4 + 2], bl[nt2 * 4 + 3],
                      st + 3 * GT_TILE + off);
            }
#pragma unroll
            for (int mt = 0; mt < 4; ++mt) {
                const int off = swz((a_row + mt * 16) * 128 + (ks * 16 + a_k8) * 2);
                uint32_t ah[4], al[4];
                ldsm4(ah[0], ah[1], ah[2], ah[3], st + 0 * GT_TILE + off);
                ldsm4(al[0], al[1], al[2], al[3], st + 1 * GT_TILE + off);
#pragma unroll
                for (int nt = 0; nt < 4; ++nt) {
                    mma16816(acc[mt][nt], ah, bh[nt * 2 + 0], bh[nt * 2 + 1]);
                    mma16816(acc[mt][nt], ah, bl[nt * 2 + 0], bl[nt * 2 + 1]);
                    mma16816(acc[mt][nt], al, bh[nt * 2 + 0], bh[nt * 2 + 1]);
                }
            }
        }
        __syncthreads();
    }

    // epilogue: fragment -> fused exp -> stage SMEM
#pragma unroll
    for (int mt = 0; mt < 4; ++mt) {
        const int r0 = warp_m * 64 + mt * 16 + (lane >> 2);
        const int r1 = r0 + 8;
        const float s0 = sqa[r0], s1 = sqa[r1];
#pragma unroll
        for (int nt = 0; nt < 4; ++nt) {
            const int c = warp_n * 32 + nt * 8 + 2 * (lane & 3);
            const float q0 = sqb[c], q1 = sqb[c + 1];
            const float* d = acc[mt][nt];
            stage[r0 * 132 + c]     = __expf(-fmaxf(s0 + q0 - 2.f * d[0], 0.f));
            stage[r0 * 132 + c + 1] = __expf(-fmaxf(s0 + q1 - 2.f * d[1], 0.f));
            stage[r1 * 132 + c]     = __expf(-fmaxf(s1 + q0 - 2.f * d[2], 0.f));
            stage[r1 * 132 + c + 1] = __expf(-fmaxf(s1 + q1 - 2.f * d[3], 0.f));
        }
    }
    __syncthreads();

    float* cb = corr + (size_t)b * TT * TT;
#pragma unroll
    for (int m = 0; m < 16; ++m) {
        const int idx = m * 256 + tid;
        const int row = idx >> 5;
        const int c4 = (idx & 31) * 4;
        float4 v = *reinterpret_cast<float4*>(&stage[row * 132 + c4]);
        *reinterpret_cast<float4*>(cb + (size_t)(tib + row) * TT + tjb + c4) = v;
    }
    if (ti != tj) {
        for (int m = 0; m < 64; ++m) {
            const int idx = m * 256 + tid;
            const int c = idx >> 7;
            const int r = idx & 127;
            cb[(size_t)(tjb + c) * TT + tib + r] = stage[r * 132 + c];
        }
    }
}

// ---------------------------------------------------------------------------
extern "C" void kernel_launch(void* const* d_in, const int* in_sizes, int n_in,
                              void* d_out, int out_size)
{
    const float* x   = (const float*)d_in[0];
    const float* W1  = (const float*)d_in[1];
    const float* b1  = (const float*)d_in[2];
    const float* W2  = (const float*)d_in[3];
    const float* b2  = (const float*)d_in[4];
    const float* Wih = (const float*)d_in[5];
    const float* Whh = (const float*)d_in[6];

    float* out  = (float*)d_out;
    float* corr = out;                                 // [B, T, T]
    float* p    = out + (size_t)BB * TT * TT;          // [B, T, H]

    const size_t rnn_smem = (size_t)(576 + SW * HH) * sizeof(float);   // ~98.3 KB
    cudaFuncSetAttribute(rnn_kernel,      cudaFuncAttributeMaxDynamicSharedMemorySize, (int)rnn_smem);
    cudaFuncSetAttribute(gram_mma_kernel, cudaFuncAttributeMaxDynamicSharedMemorySize, GT_SMEM);

    rnn_kernel<<<BB, 256, rnn_smem>>>(x, W1, b1, W2, b2, Wih, Whh, p);
    prep_kernel<<<(BB * TT) / 8, 256>>>(p);
    gram_mma_kernel<<<dim3(36, BB), 256, GT_SMEM>>>(corr);
}